// round 5
// baseline (speedup 1.0000x reference)
#include <cuda_runtime.h>
#include <cuda_fp16.h>
#include <math.h>
#include <stdint.h>

constexpr int B_ = 8;
constexpr int N_ = 512;
constexpr int D_ = 256;

constexpr int CLUSTER  = 8;
constexpr int CHUNK    = 32;   // D/CLUSTER
constexpr int IOU_ROWS = 64;   // 2D/CLUSTER
constexpr int COU_ROWS = 32;   // D/CLUSTER
constexpr int MTHREADS = 256;
constexpr int NCLU     = 4;    // clusters; each handles 2 batches

// ---- device scratch ----
__device__ __align__(128) float g_dinv[B_ * N_];
__device__ __align__(128) float g_normT[B_ * N_ * N_];
__device__ __align__(128) float g_pre_iou[B_ * N_ * 2 * D_];
__device__ __align__(128) float g_pre_cou[B_ * N_ * D_];

// ---------------- dinv ----------------
__global__ void k_dinv(const float* __restrict__ adj) {
    int bi = blockIdx.x;
    const float* row = adj + (size_t)bi * N_;
    float s = 0.f;
    for (int j = threadIdx.x; j < N_; j += blockDim.x) s += row[j];
    __shared__ float sm[8];
    #pragma unroll
    for (int o = 16; o; o >>= 1) s += __shfl_down_sync(~0u, s, o);
    if ((threadIdx.x & 31) == 0) sm[threadIdx.x >> 5] = s;
    __syncthreads();
    if (threadIdx.x == 0) {
        float v = 0.f;
        for (int w = 0; w < 8; w++) v += sm[w];
        g_dinv[bi] = (v != 0.f) ? (1.f / v) : 0.f;
    }
}

// ---------------- normT[b][i][j] = adj[b][j][i] * dinv[b][i] ----------------
__global__ void k_transpose(const float* __restrict__ adj) {
    __shared__ float tile[32][33];
    int b = blockIdx.z;
    int i0 = blockIdx.x * 32, j0 = blockIdx.y * 32;
    int tx = threadIdx.x, ty = threadIdx.y;
    const float* A = adj + (size_t)b * N_ * N_;
    #pragma unroll
    for (int q = 0; q < 32; q += 8)
        tile[ty + q][tx] = A[(size_t)(j0 + ty + q) * N_ + i0 + tx];
    __syncthreads();
    float* T = g_normT + (size_t)b * N_ * N_;
    #pragma unroll
    for (int q = 0; q < 32; q += 8) {
        int i = i0 + ty + q;
        T[(size_t)i * N_ + j0 + tx] = tile[tx][ty + q] * g_dinv[b * N_ + i];
    }
}

// ---------------- pre GEMM ----------------
template <int P>
__global__ void k_gemm(const float* __restrict__ X, const float* __restrict__ W,
                       const float* __restrict__ b1, const float* __restrict__ b2,
                       float* __restrict__ C) {
    constexpr int BM = 128, BP = 128, BK = 16;
    __shared__ float As[BK][BM];
    __shared__ float Bs[BK][BP];
    int m0 = blockIdx.y * BM, p0 = blockIdx.x * BP;
    int t = threadIdx.x;
    int tx = t % 16, ty = t / 16;
    float acc[8][8] = {};
    int lrow = t >> 2, lkv = (t & 3) * 4;

    for (int k0 = 0; k0 < D_; k0 += BK) {
        #pragma unroll
        for (int r = 0; r < BM; r += 64) {
            float4 v = *(const float4*)&X[(size_t)(m0 + lrow + r) * D_ + k0 + lkv];
            As[lkv + 0][lrow + r] = v.x; As[lkv + 1][lrow + r] = v.y;
            As[lkv + 2][lrow + r] = v.z; As[lkv + 3][lrow + r] = v.w;
        }
        #pragma unroll
        for (int r = 0; r < BP; r += 64) {
            float4 v = *(const float4*)&W[(size_t)(p0 + lrow + r) * D_ + k0 + lkv];
            Bs[lkv + 0][lrow + r] = v.x; Bs[lkv + 1][lrow + r] = v.y;
            Bs[lkv + 2][lrow + r] = v.z; Bs[lkv + 3][lrow + r] = v.w;
        }
        __syncthreads();
        #pragma unroll
        for (int k = 0; k < BK; k++) {
            float a[8], bb[8];
            *(float4*)&a[0]  = *(const float4*)&As[k][ty * 8];
            *(float4*)&a[4]  = *(const float4*)&As[k][ty * 8 + 4];
            *(float4*)&bb[0] = *(const float4*)&Bs[k][tx * 8];
            *(float4*)&bb[4] = *(const float4*)&Bs[k][tx * 8 + 4];
            #pragma unroll
            for (int im = 0; im < 8; im++)
                #pragma unroll
                for (int ip = 0; ip < 8; ip++)
                    acc[im][ip] += a[im] * bb[ip];
        }
        __syncthreads();
    }
    int pbase = p0 + tx * 8;
    float bs[8];
    #pragma unroll
    for (int ip = 0; ip < 8; ip++) bs[ip] = b1[pbase + ip] + b2[pbase + ip];
    #pragma unroll
    for (int im = 0; im < 8; im++) {
        size_t off = (size_t)(m0 + ty * 8 + im) * P + pbase;
        #pragma unroll
        for (int ip = 0; ip < 8; ip++) C[off + ip] = acc[im][ip] + bs[ip];
    }
}

// ---------------- main kernel: 4 clusters x 8 CTAs, 2 batches per cluster ----
// SMEM layout (float offsets)
constexpr int fH    = 0;       // [2][512][32]       32768 floats
constexpr int fROW  = 32768;   // [2][2][512]        2048
constexpr int fXPAR = 34816;   // [2][2][256]        1024
constexpr int fV    = 35840;   // [2][256]           512
constexpr int fZ    = 36352;   // [2][256]           512
constexpr int fREDA = 36864;   // [512]
constexpr int fREDB = 37376;   // [512]
constexpr int fSRED = 37888;   // [2][1024]          2048
constexpr int fS1   = 39936;   // [2][128]           256
constexpr int fHNEW = 40192;   // [2][32]            64
constexpr int WIOU_B = 161024; // half[256*64]       32768 B
constexpr int WCOU_B = 193792; // half[256*32]       16384 B
constexpr int SMEM_BYTES = 210176;

__device__ __forceinline__ void cluster_arrive() {
    asm volatile("barrier.cluster.arrive.aligned;" ::: "memory");
}
__device__ __forceinline__ void cluster_wait() {
    asm volatile("barrier.cluster.wait.aligned;" ::: "memory");
}
__device__ __forceinline__ void bcast_f32(float* localp, float val) {
    uint32_t l = (uint32_t)__cvta_generic_to_shared(localp);
    uint32_t bits = __float_as_uint(val);
    #pragma unroll
    for (int dst = 0; dst < CLUSTER; dst++) {
        uint32_t r;
        asm("mapa.shared::cluster.u32 %0, %1, %2;" : "=r"(r) : "r"(l), "r"(dst));
        asm volatile("st.shared::cluster.u32 [%0], %1;" :: "r"(r), "r"(bits));
    }
}

extern __shared__ char smem_raw[];

__global__ void __cluster_dims__(CLUSTER, 1, 1) __launch_bounds__(MTHREADS, 1)
k_main(const float* __restrict__ h_e,
       const float* __restrict__ W_iouh,
       const float* __restrict__ W_couh,
       float* __restrict__ out) {
    float* smf = (float*)smem_raw;
    __half* wiou = (__half*)(smem_raw + WIOU_B);   // [256][64] d-major
    __half* wcou = (__half*)(smem_raw + WCOU_B);   // [256][32] d-major
    const __half2* wiou2 = (const __half2*)wiou;
    const __half2* wcou2 = (const __half2*)wcou;

    const int t = threadIdx.x;
    const int rank = blockIdx.x % CLUSTER;
    const int c = blockIdx.x / CLUSTER;   // cluster id: batches c, c+4

    float* h_[2]    = { smf + fH,            smf + fH + 16384 };
    float* row_[2]  = { smf + fROW,          smf + fROW + 1024 };   // [2][512] each
    float* xp_[2]   = { smf + fXPAR,         smf + fXPAR + 512 };   // [2][256] each
    float* v_[2]    = { smf + fV,            smf + fV + 256 };
    float* z_[2]    = { smf + fZ,            smf + fZ + 256 };
    float* red_[2]  = { smf + fREDA,         smf + fREDB };
    float* sred_[2] = { smf + fSRED,         smf + fSRED + 1024 };
    float* s1_[2]   = { smf + fS1,           smf + fS1 + 128 };
    float* hn_[2]   = { smf + fHNEW,         smf + fHNEW + 32 };
    const int bb[2] = { c, c + 4 };

    // skip-one aggregation into sred_[ib]
    auto sgemv = [&](int ib, const float* rowp, int skip) {
        int c4 = (t & 7) * 4, g = t >> 3;
        const float* hp = h_[ib];
        float4 acc = make_float4(0.f, 0.f, 0.f, 0.f);
        #pragma unroll
        for (int jj = 0; jj < 16; jj++) {
            int r = g + 32 * jj;
            if (r != skip) {
                float rv = rowp[r];
                float4 hv = *(const float4*)&hp[r * CHUNK + c4];
                acc.x += rv * hv.x; acc.y += rv * hv.y;
                acc.z += rv * hv.z; acc.w += rv * hv.w;
            }
        }
        *(float4*)&sred_[ib][g * CHUNK + c4] = acc;
    };

    // ---- init ----
    {
        for (int ib = 0; ib < 2; ib++) {
            const float* src = h_e + (size_t)bb[ib] * N_ * D_ + rank * CHUNK;
            for (int idx = t; idx < N_ * CHUNK; idx += MTHREADS) {
                int j = idx / CHUNK, cc = idx % CHUNK;
                h_[ib][j * CHUNK + cc] = src[(size_t)j * D_ + cc];
            }
            if (t < 128) {  // rows 0 and 1 into bufs 0 and 1
                *(float4*)&row_[ib][t * 4] =
                    *(const float4*)&g_normT[((size_t)bb[ib] * N_) * N_ + t * 4];
                *(float4*)&row_[ib][512 + t * 4] =
                    *(const float4*)&g_normT[((size_t)bb[ib] * N_ + 1) * N_ + t * 4];
            }
        }
        const float* ws = W_iouh + (size_t)(rank * IOU_ROWS) * D_;
        for (int idx = t; idx < IOU_ROWS * D_; idx += MTHREADS) {
            int p = idx / D_, d = idx % D_;
            wiou[d * IOU_ROWS + p] = __float2half(ws[idx]);
        }
        const float* wc = W_couh + (size_t)(rank * COU_ROWS) * D_;
        for (int idx = t; idx < COU_ROWS * D_; idx += MTHREADS) {
            int p = idx / D_, d = idx % D_;
            wcou[d * COU_ROWS + p] = __float2half(wc[idx]);
        }
    }
    __syncthreads();

    const int ibt = t >> 7;      // batch slot handled by this thread in finish stages
    const int tt  = t & 127;

    float pre = 0.f, pre2 = 0.f;

    // ---- bootstrap: x_par_0 for both batches ----
    sgemv(0, &row_[0][0], -1);
    sgemv(1, &row_[1][0], -1);
    __syncthreads();
    {   // parallel sred reduce: t<128 -> A, t>=128 -> B
        int cc = tt & 31, q = tt >> 5;
        float s = 0.f;
        #pragma unroll
        for (int k = 0; k < 8; k++) s += sred_[ibt][(q * 8 + k) * CHUNK + cc];
        s1_[ibt][q * CHUNK + cc] = s;
    }
    __syncthreads();
    if (tt < CHUNK) {
        float* s1p = s1_[ibt];
        float s = s1p[tt] + s1p[32 + tt] + s1p[64 + tt] + s1p[96 + tt];
        bcast_f32(&xp_[ibt][rank * CHUNK + tt], s);
    }
    cluster_arrive();
    if (tt < IOU_ROWS)
        pre = g_pre_iou[((size_t)bb[ibt] * N_) * (2 * D_) + rank * IOU_ROWS + tt];
    if (tt < COU_ROWS)
        pre2 = g_pre_cou[((size_t)bb[ibt] * N_) * D_ + rank * COU_ROWS + tt];
    cluster_wait();

    for (int i = 0; i < N_; i++) {
        const int cur = i & 1;
        const int nxt = cur ^ 1;

        // ---- phase 2 GEMVs (both batches, all threads) ----
        #pragma unroll
        for (int ib = 0; ib < 2; ib++) {
            int pp = t & 31, q = t >> 5;
            const float* xp = xp_[ib] + cur * D_ + q * 32;
            float a0 = 0.f, a1 = 0.f;
            #pragma unroll
            for (int dd = 0; dd < 32; dd++) {
                float xv = xp[dd];
                float2 wf = __half22float2(wiou2[(q * 32 + dd) * 32 + pp]);
                a0 += xv * wf.x; a1 += xv * wf.y;
            }
            red_[ib][q * IOU_ROWS + 2 * pp]     = a0;
            red_[ib][q * IOU_ROWS + 2 * pp + 1] = a1;
        }
        __syncthreads();
        // finish iou (A on t<128, B on t>=128)
        if (tt < IOU_ROWS) {
            float s = pre;
            const float* rp = red_[ibt];
            #pragma unroll
            for (int q = 0; q < 8; q++) s += rp[q * IOU_ROWS + tt];
            float sg = 1.f / (1.f + __expf(-s));
            if (rank < 4) {
                int gp = rank * IOU_ROWS + tt;
                bcast_f32(&v_[ibt][gp], xp_[ibt][cur * D_ + gp] * sg);
            } else {
                bcast_f32(&z_[ibt][(rank - 4) * IOU_ROWS + tt], sg);
            }
        }
        cluster_arrive();
        if (i + 1 < N_) {
            sgemv(0, &row_[0][nxt * N_], i);
            sgemv(1, &row_[1][nxt * N_], i);
        }
        cluster_wait();  // v,z visible

        // ---- phase 3 GEMVs ----
        #pragma unroll
        for (int ib = 0; ib < 2; ib++) {
            int pp = t & 15, q = t >> 4;
            const float* vp = v_[ib] + q * 16;
            float a0 = 0.f, a1 = 0.f;
            #pragma unroll
            for (int dd = 0; dd < 16; dd++) {
                float vv = vp[dd];
                float2 wf = __half22float2(wcou2[(q * 16 + dd) * 16 + pp]);
                a0 += vv * wf.x; a1 += vv * wf.y;
            }
            red_[ib][q * COU_ROWS + 2 * pp]     = a0;
            red_[ib][q * COU_ROWS + 2 * pp + 1] = a1;
        }
        __syncthreads();
        if (tt < COU_ROWS) {
            float s = pre2;
            const float* rp = red_[ibt];
            #pragma unroll
            for (int q = 0; q < 16; q++) s += rp[q * COU_ROWS + tt];
            float hc  = tanhf(s);
            float xpv = xp_[ibt][cur * D_ + rank * COU_ROWS + tt];
            float zz  = z_[ibt][rank * COU_ROWS + tt];
            float hn  = zz * xpv + (1.f - zz) * hc;
            h_[ibt][i * CHUNK + tt] = hn;
            hn_[ibt][tt] = hn;
            out[((size_t)bb[ibt] * N_ + i) * D_ + rank * COU_ROWS + tt] = hn;
        }
        __syncthreads();  // hnew + sred visible

        if (i + 1 < N_) {
            {   // parallel sred reduce
                int cc = tt & 31, q = tt >> 5;
                float s = 0.f;
                #pragma unroll
                for (int k = 0; k < 8; k++) s += sred_[ibt][(q * 8 + k) * CHUNK + cc];
                s1_[ibt][q * CHUNK + cc] = s;
            }
            __syncthreads();
            if (tt < CHUNK) {
                float* s1p = s1_[ibt];
                float s = s1p[tt] + s1p[32 + tt] + s1p[64 + tt] + s1p[96 + tt]
                        + row_[ibt][nxt * N_ + i] * hn_[ibt][tt];
                bcast_f32(&xp_[ibt][nxt * D_ + rank * CHUNK + tt], s);
            }
            cluster_arrive();
            if (tt < IOU_ROWS)
                pre = g_pre_iou[((size_t)bb[ibt] * N_ + i + 1) * (2 * D_) + rank * IOU_ROWS + tt];
            if (tt < COU_ROWS)
                pre2 = g_pre_cou[((size_t)bb[ibt] * N_ + i + 1) * D_ + rank * COU_ROWS + tt];
            if (i + 2 < N_) {  // row i+2 into buf cur (t<128 -> A, t>=128 -> B)
                *(float4*)&row_[ibt][cur * N_ + tt * 4] =
                    *(const float4*)&g_normT[((size_t)bb[ibt] * N_ + i + 2) * N_ + tt * 4];
            }
            cluster_wait();  // x_par_{i+1} visible
        }
    }
}

extern "C" void kernel_launch(void* const* d_in, const int* in_sizes, int n_in,
                              void* d_out, int out_size) {
    const float* h_e    = (const float*)d_in[0];
    const float* adj    = (const float*)d_in[1];
    const float* W_ioux = (const float*)d_in[2];
    const float* b_ioux = (const float*)d_in[3];
    const float* W_iouh = (const float*)d_in[4];
    const float* b_iouh = (const float*)d_in[5];
    const float* W_coux = (const float*)d_in[6];
    const float* b_coux = (const float*)d_in[7];
    const float* W_couh = (const float*)d_in[8];
    const float* b_couh = (const float*)d_in[9];
    float* out = (float*)d_out;

    float* pre_iou; cudaGetSymbolAddress((void**)&pre_iou, g_pre_iou);
    float* pre_cou; cudaGetSymbolAddress((void**)&pre_cou, g_pre_cou);

    k_dinv<<<B_ * N_, 256>>>(adj);
    {
        dim3 grid(N_ / 32, N_ / 32, B_), blk(32, 8);
        k_transpose<<<grid, blk>>>(adj);
    }
    {
        dim3 grid((2 * D_) / 128, (B_ * N_) / 128);
        k_gemm<2 * D_><<<grid, 256>>>(h_e, W_ioux, b_ioux, b_iouh, pre_iou);
    }
    {
        dim3 grid(D_ / 128, (B_ * N_) / 128);
        k_gemm<D_><<<grid, 256>>>(h_e, W_coux, b_coux, b_couh, pre_cou);
    }
    static bool attr_set = false;
    if (!attr_set) {
        cudaFuncSetAttribute(k_main, cudaFuncAttributeMaxDynamicSharedMemorySize,
                             SMEM_BYTES);
        attr_set = true;
    }
    k_main<<<NCLU * CLUSTER, MTHREADS, SMEM_BYTES>>>(h_e, W_iouh, W_couh, out);
}